// round 15
// baseline (speedup 1.0000x reference)
#include <cuda_runtime.h>

// HarmonicOscillator — confirmed numerics:
//   v = f0_up * fl32(1/22050); interp = two muls + add (no contraction);
//   cumsum = XLA ReduceWindowRewriter(base=16), serial 16-folds per tile,
//   levels 262144->16384->1024->64->4 (terminal serial), combine
//   out = fl(outer_excl + inner), row 0 exact.
// R15: k_main issue-slot diet — 1 of 4 pairs/iter via packed poly sine
//      (no MUFU/pk/upk), LDS.128 amp loads. Scan pipeline = R12 (best).

#define BATCH 8
#define FRAMES 512
#define NH 64
#define NS 262144              // 512*512
#define ROWS 16384             // NS/16

__device__ float g_P0[BATCH][NS];
__device__ float g_P1[BATCH][ROWS];
__device__ float g_T2[BATCH][1024];
__device__ float g_S2[BATCH][1024];

typedef unsigned long long u64;

__device__ __forceinline__ u64 pk(float lo, float hi) {
    u64 r; asm("mov.b64 %0,{%1,%2};" : "=l"(r) : "f"(lo), "f"(hi)); return r;
}
__device__ __forceinline__ void upk(u64 v, float& lo, float& hi) {
    asm("mov.b64 {%0,%1},%2;" : "=f"(lo), "=f"(hi) : "l"(v));
}
__device__ __forceinline__ u64 fma2(u64 a, u64 b, u64 c) {
    u64 d; asm("fma.rn.f32x2 %0,%1,%2,%3;" : "=l"(d) : "l"(a), "l"(b), "l"(c)); return d;
}
__device__ __forceinline__ u64 mul2(u64 a, u64 b) {
    u64 d; asm("mul.rn.f32x2 %0,%1,%2;" : "=l"(d) : "l"(a), "l"(b)); return d;
}
__device__ __forceinline__ u64 sub2(u64 a, u64 b) {
    u64 d; asm("sub.rn.f32x2 %0,%1,%2;" : "=l"(d) : "l"(a), "l"(b)); return d;
}

__device__ __forceinline__ float interp_c() {
    return (float)(511.0 / 262143.0);
}

// ---- k1: P0 tile prefixes + P1 level-1 prefixes + T2 tile sums ----
__global__ void __launch_bounds__(256) k1(const float* __restrict__ f0) {
    const int b = blockIdx.y;
    const int t = threadIdx.x;                  // 0..255
    const int row = blockIdx.x * 256 + t;
    const float* fr = f0 + b * FRAMES;

    const int base = row * 16;

    float posJ = __fmul_rn((float)base, interp_c());
    const int j = (int)floorf(posJ);
    const float v0 = __ldg(fr + j);
    const float v1 = __ldg(fr + min(j + 1, FRAMES - 1));
    const float v2 = __ldg(fr + min(j + 2, FRAMES - 1));

    float x[16];
    float acc = 0.0f;
    #pragma unroll
    for (int c = 0; c < 16; ++c) {
        const int n = base + c;
        float nf  = (float)n;
        float pos = __fmul_rn(nf, interp_c());
        float fi0 = floorf(pos);
        int   i0  = (int)fi0;
        int   i1  = min(i0 + 1, FRAMES - 1);
        float w   = __fadd_rn(pos, -fi0);
        float omw = __fadd_rn(1.0f, -w);
        float a  = (i0 == j)     ? v0 : v1;
        float cc = (i1 == j + 1) ? v1 : v2;
        float up  = __fadd_rn(__fmul_rn(a, omw), __fmul_rn(cc, w));
        const float RECIP_SR = (float)(1.0 / 22050.0);
        float v   = __fmul_rn(up, RECIP_SR);
        acc = __fadd_rn(acc, v);
        x[c] = acc;
    }
    float4* dst = (float4*)(g_P0[b] + base);
    dst[0] = make_float4(x[0],  x[1],  x[2],  x[3]);
    dst[1] = make_float4(x[4],  x[5],  x[6],  x[7]);
    dst[2] = make_float4(x[8],  x[9],  x[10], x[11]);
    dst[3] = make_float4(x[12], x[13], x[14], x[15]);

    __shared__ float sT1[256];
    __shared__ float sP1[256];
    sT1[t] = acc;
    __syncthreads();
    if (t < 16) {
        float a2 = 0.0f;
        #pragma unroll
        for (int c = 0; c < 16; ++c) {
            a2 = __fadd_rn(a2, sT1[t * 16 + c]);
            sP1[t * 16 + c] = a2;
        }
        g_T2[b][blockIdx.x * 16 + t] = a2;
    }
    __syncthreads();
    g_P1[b][row] = sP1[t];
}

// ---- k2: levels 2..4, emit scan2 (1024/batch) ----
__global__ void k2() {
    const int b = blockIdx.x;
    const int t = threadIdx.x;                  // 0..127
    __shared__ float sP2[1024];
    __shared__ float sS3[64];
    __shared__ float sP4[4];

    if (t < 64) {
        float a = 0.0f;
        #pragma unroll
        for (int c = 0; c < 16; ++c) {
            a = __fadd_rn(a, g_T2[b][t * 16 + c]);
            sP2[t * 16 + c] = a;
        }
    }
    __syncthreads();
    if (t < 4) {
        float a = 0.0f;
        #pragma unroll
        for (int c = 0; c < 16; ++c) {
            a = __fadd_rn(a, sP2[(t * 16 + c) * 16 + 15]);
            sS3[t * 16 + c] = a;
        }
    }
    __syncthreads();
    if (t == 0) {
        float a = 0.0f;
        #pragma unroll
        for (int c = 0; c < 4; ++c) {
            a = __fadd_rn(a, sS3[c * 16 + 15]);
            sP4[c] = a;
        }
    }
    __syncthreads();
    if (t < 48) {
        int m = t + 16;
        sS3[m] = __fadd_rn(sP4[(m >> 4) - 1], sS3[m]);
    }
    __syncthreads();
    #pragma unroll
    for (int k = 0; k < 8; ++k) {
        int jj = t + k * 128;
        float p2 = sP2[jj];
        g_S2[b][jj] = (jj < 16) ? p2 : __fadd_rn(sS3[(jj >> 4) - 1], p2);
    }
}

// ---- S reconstruction (exact reference fl nesting) ----
__device__ __forceinline__ float recon_S(int b, int n) {
    float p0 = g_P0[b][n];
    const int r1i = n >> 4;
    if (r1i == 0) return p0;
    const int j = r1i - 1;
    float p1 = g_P1[b][j];
    const int r2 = j >> 4;
    float s1 = (r2 == 0) ? p1 : __fadd_rn(g_S2[b][r2 - 1], p1);
    return __fadd_rn(s1, p0);
}

// ---- k_main: packed f32x2 synthesis, 2 samples/thread, hybrid sin ----
__global__ void __launch_bounds__(128) k_main(const float* __restrict__ amps,
                                              float* __restrict__ out) {
    const int b = blockIdx.y;
    const int n0 = blockIdx.x * 256;
    const int t = threadIdx.x;                   // 0..127
    const int nA = n0 + t;
    const int nB = n0 + t + 128;

    float posF = __fmul_rn((float)n0, interp_c());
    const int i0f = (int)floorf(posF);

    __shared__ __align__(16) u64 sA0[2][32];
    __shared__ __align__(16) u64 sDF[2][32];
    if (t < 64) {
        int g = t >> 5;
        int s = t & 31;
        int r0 = min(i0f + g, FRAMES - 1);
        int r1 = min(r0 + 1, FRAMES - 1);
        const u64* rowA = (const u64*)(amps + ((size_t)b * FRAMES + r0) * NH);
        const u64* rowB = (const u64*)(amps + ((size_t)b * FRAMES + r1) * NH);
        u64 a0 = __ldg(rowA + s);
        u64 a1 = __ldg(rowB + s);
        sA0[g][s] = a0;
        sDF[g][s] = sub2(a1, a0);
    }

    const float TWO_PI_F = 6.283185307179586f;
    float phA = __fmul_rn(recon_S(b, nA), TWO_PI_F);
    float phB = __fmul_rn(recon_S(b, nB), TWO_PI_F);

    float posA = __fmul_rn((float)nA, interp_c());
    float fA   = floorf(posA);
    int   iA   = (int)fA;
    float wA   = __fadd_rn(posA, -fA);
    const int gA = iA - i0f;

    float posB = __fmul_rn((float)nB, interp_c());
    float fB   = floorf(posB);
    int   iB   = (int)fB;
    float wB   = __fadd_rn(posB, -fB);
    const int gB = iB - i0f;

    __syncthreads();

    // 2pi Cody-Waite (MUFU pairs)
    const float INV2PI = (float)(1.0 / 6.283185307179586);
    const float C1 = 6.283185482025146484375f;
    const float C2 = -1.7484556e-7f;
    const float MAGIC = 12582912.0f;             // 1.5 * 2^23
    // pi half-turn reduction (poly pair)
    const float INVPI = 0.31830987334251403809f; // f32(1/pi)
    const float PI1 = 3.14159274101257324219f;   // f32(pi)
    const float PI2 = -8.742277657e-8f;          // pi - PI1

    u64 wA2 = pk(wA, wA);
    u64 wB2 = pk(wB, wB);
    u64 pA2 = pk(phA, phA);
    u64 pB2 = pk(phB, phB);
    u64 IV2 = pk(INV2PI, INV2PI);
    u64 MG2 = pk(MAGIC, MAGIC);
    u64 C1n = pk(-C1, -C1);
    u64 C2n = pk(-C2, -C2);
    u64 IVP = pk(INVPI, INVPI);
    u64 P1n = pk(-PI1, -PI1);
    u64 P2n = pk(-PI2, -PI2);
    const u64 C3_2 = pk(-1.6666667e-1f, -1.6666667e-1f);
    const u64 C5_2 = pk( 8.3333310e-3f,  8.3333310e-3f);
    const u64 C7_2 = pk(-1.9841271e-4f, -1.9841271e-4f);
    const u64 C9_2 = pk( 2.7557314e-6f,  2.7557314e-6f);

    u64 accA0 = pk(0.0f, 0.0f), accA1 = pk(0.0f, 0.0f);
    u64 accB0 = pk(0.0f, 0.0f), accB1 = pk(0.0f, 0.0f);

    #pragma unroll
    for (int q = 0; q < NH / 4; ++q) {
        u64 h0 = pk((float)(4 * q + 1), (float)(4 * q + 2));
        u64 h1 = pk((float)(4 * q + 3), (float)(4 * q + 4));

        ulonglong2 a0A = ((const ulonglong2*)sA0[gA])[q];
        ulonglong2 dfA = ((const ulonglong2*)sDF[gA])[q];
        ulonglong2 a0B = ((const ulonglong2*)sA0[gB])[q];
        ulonglong2 dfB = ((const ulonglong2*)sDF[gB])[q];

        u64 ampA0 = fma2(wA2, dfA.x, a0A.x);
        u64 ampA1 = fma2(wA2, dfA.y, a0A.y);
        u64 ampB0 = fma2(wB2, dfB.x, a0B.x);
        u64 ampB1 = fma2(wB2, dfB.y, a0B.y);

        {   // MUFU pair: sample A, harmonics 4q+1, 4q+2
            u64 pr = mul2(pA2, h0);
            u64 tt = fma2(pr, IV2, MG2);
            u64 kf = sub2(tt, MG2);
            u64 r  = fma2(kf, C1n, pr);
            r      = fma2(kf, C2n, r);
            float rl, rh; upk(r, rl, rh);
            accA0  = fma2(pk(__sinf(rl), __sinf(rh)), ampA0, accA0);
        }
        {   // MUFU pair: sample B, harmonics 4q+1, 4q+2
            u64 pr = mul2(pB2, h0);
            u64 tt = fma2(pr, IV2, MG2);
            u64 kf = sub2(tt, MG2);
            u64 r  = fma2(kf, C1n, pr);
            r      = fma2(kf, C2n, r);
            float rl, rh; upk(r, rl, rh);
            accB0  = fma2(pk(__sinf(rl), __sinf(rh)), ampB0, accB0);
        }
        {   // MUFU pair: sample A, harmonics 4q+3, 4q+4
            u64 pr = mul2(pA2, h1);
            u64 tt = fma2(pr, IV2, MG2);
            u64 kf = sub2(tt, MG2);
            u64 r  = fma2(kf, C1n, pr);
            r      = fma2(kf, C2n, r);
            float rl, rh; upk(r, rl, rh);
            accA1  = fma2(pk(__sinf(rl), __sinf(rh)), ampA1, accA1);
        }
        {   // POLY pair (no MUFU, fully packed): sample B, harmonics 4q+3, 4q+4
            u64 pr = mul2(pB2, h1);
            u64 tt = fma2(pr, IVP, MG2);        // round(pr/pi) + MAGIC
            u64 kf = sub2(tt, MG2);             // half-turn count m (>= 0)
            u64 r  = fma2(kf, P1n, pr);
            r      = fma2(kf, P2n, r);          // |r| <= ~1.67
            u64 z  = mul2(r, r);
            u64 P  = fma2(z, C9_2, C7_2);
            P      = fma2(z, P, C5_2);
            P      = fma2(z, P, C3_2);
            u64 rz = mul2(r, z);
            u64 s  = fma2(rz, P, r);            // sin(r)
            u64 sgn = (tt & 0x0000000100000001ULL) << 31;  // parity of m, both lanes
            s ^= sgn;                            // sin(pr) = (-1)^m sin(r)
            accB1  = fma2(s, ampB1, accB1);
        }
    }
    float a0l, a0h, a1l, a1h, b0l, b0h, b1l, b1h;
    upk(accA0, a0l, a0h); upk(accA1, a1l, a1h);
    upk(accB0, b0l, b0h); upk(accB1, b1l, b1h);
    out[(size_t)b * NS + nA] = (a0l + a0h) + (a1l + a1h);
    out[(size_t)b * NS + nB] = (b0l + b0h) + (b1l + b1h);
}

extern "C" void kernel_launch(void* const* d_in, const int* in_sizes, int n_in,
                              void* d_out, int out_size) {
    const float* f0   = (const float*)d_in[0];   // (8, 512)
    const float* amps = (const float*)d_in[1];   // (8, 512, 64)
    float* out = (float*)d_out;                  // (8, 262144)

    k1<<<dim3(ROWS / 256, BATCH), 256>>>(f0);
    k2<<<BATCH, 128>>>();
    k_main<<<dim3(NS / 256, BATCH), 128>>>(amps, out);
}

// round 16
// speedup vs baseline: 1.0964x; 1.0964x over previous
#include <cuda_runtime.h>

// HarmonicOscillator — confirmed numerics (rel_err 2.6e-7):
//   v = f0_up * fl32(1/22050); interp = two muls + add (no contraction);
//   cumsum = XLA ReduceWindowRewriter(base=16), serial 16-folds per tile,
//   levels 262144->16384->1024->64->4 (terminal serial), combine
//   out = fl(outer_excl + inner), row 0 exact.
// R16: revert poly (R15 regression). k_main = 4 samples/thread, 512-sample
//      blocks (prolog amortization: 35% -> ~20% of block time), LDS.128
//      staging reads kept. All-MUFU sin path (validated numerics).

#define BATCH 8
#define FRAMES 512
#define NH 64
#define NS 262144              // 512*512
#define ROWS 16384             // NS/16

__device__ float g_P0[BATCH][NS];
__device__ float g_P1[BATCH][ROWS];
__device__ float g_T2[BATCH][1024];
__device__ float g_S2[BATCH][1024];

typedef unsigned long long u64;

__device__ __forceinline__ u64 pk(float lo, float hi) {
    u64 r; asm("mov.b64 %0,{%1,%2};" : "=l"(r) : "f"(lo), "f"(hi)); return r;
}
__device__ __forceinline__ void upk(u64 v, float& lo, float& hi) {
    asm("mov.b64 {%0,%1},%2;" : "=f"(lo), "=f"(hi) : "l"(v));
}
__device__ __forceinline__ u64 fma2(u64 a, u64 b, u64 c) {
    u64 d; asm("fma.rn.f32x2 %0,%1,%2,%3;" : "=l"(d) : "l"(a), "l"(b), "l"(c)); return d;
}
__device__ __forceinline__ u64 mul2(u64 a, u64 b) {
    u64 d; asm("mul.rn.f32x2 %0,%1,%2;" : "=l"(d) : "l"(a), "l"(b)); return d;
}
__device__ __forceinline__ u64 sub2(u64 a, u64 b) {
    u64 d; asm("sub.rn.f32x2 %0,%1,%2;" : "=l"(d) : "l"(a), "l"(b)); return d;
}

__device__ __forceinline__ float interp_c() {
    return (float)(511.0 / 262143.0);
}

// ---- k1: P0 tile prefixes + P1 level-1 prefixes + T2 tile sums ----
__global__ void __launch_bounds__(256) k1(const float* __restrict__ f0) {
    const int b = blockIdx.y;
    const int t = threadIdx.x;                  // 0..255
    const int row = blockIdx.x * 256 + t;
    const float* fr = f0 + b * FRAMES;

    const int base = row * 16;

    float posJ = __fmul_rn((float)base, interp_c());
    const int j = (int)floorf(posJ);
    const float v0 = __ldg(fr + j);
    const float v1 = __ldg(fr + min(j + 1, FRAMES - 1));
    const float v2 = __ldg(fr + min(j + 2, FRAMES - 1));

    float x[16];
    float acc = 0.0f;
    #pragma unroll
    for (int c = 0; c < 16; ++c) {
        const int n = base + c;
        float nf  = (float)n;
        float pos = __fmul_rn(nf, interp_c());
        float fi0 = floorf(pos);
        int   i0  = (int)fi0;
        int   i1  = min(i0 + 1, FRAMES - 1);
        float w   = __fadd_rn(pos, -fi0);
        float omw = __fadd_rn(1.0f, -w);
        float a  = (i0 == j)     ? v0 : v1;
        float cc = (i1 == j + 1) ? v1 : v2;
        float up  = __fadd_rn(__fmul_rn(a, omw), __fmul_rn(cc, w));
        const float RECIP_SR = (float)(1.0 / 22050.0);
        float v   = __fmul_rn(up, RECIP_SR);
        acc = __fadd_rn(acc, v);
        x[c] = acc;
    }
    float4* dst = (float4*)(g_P0[b] + base);
    dst[0] = make_float4(x[0],  x[1],  x[2],  x[3]);
    dst[1] = make_float4(x[4],  x[5],  x[6],  x[7]);
    dst[2] = make_float4(x[8],  x[9],  x[10], x[11]);
    dst[3] = make_float4(x[12], x[13], x[14], x[15]);

    __shared__ float sT1[256];
    __shared__ float sP1[256];
    sT1[t] = acc;
    __syncthreads();
    if (t < 16) {
        float a2 = 0.0f;
        #pragma unroll
        for (int c = 0; c < 16; ++c) {
            a2 = __fadd_rn(a2, sT1[t * 16 + c]);
            sP1[t * 16 + c] = a2;
        }
        g_T2[b][blockIdx.x * 16 + t] = a2;
    }
    __syncthreads();
    g_P1[b][row] = sP1[t];
}

// ---- k2: levels 2..4, emit scan2 (1024/batch) ----
__global__ void k2() {
    const int b = blockIdx.x;
    const int t = threadIdx.x;                  // 0..127
    __shared__ float sP2[1024];
    __shared__ float sS3[64];
    __shared__ float sP4[4];

    if (t < 64) {
        float a = 0.0f;
        #pragma unroll
        for (int c = 0; c < 16; ++c) {
            a = __fadd_rn(a, g_T2[b][t * 16 + c]);
            sP2[t * 16 + c] = a;
        }
    }
    __syncthreads();
    if (t < 4) {
        float a = 0.0f;
        #pragma unroll
        for (int c = 0; c < 16; ++c) {
            a = __fadd_rn(a, sP2[(t * 16 + c) * 16 + 15]);
            sS3[t * 16 + c] = a;
        }
    }
    __syncthreads();
    if (t == 0) {
        float a = 0.0f;
        #pragma unroll
        for (int c = 0; c < 4; ++c) {
            a = __fadd_rn(a, sS3[c * 16 + 15]);
            sP4[c] = a;
        }
    }
    __syncthreads();
    if (t < 48) {
        int m = t + 16;
        sS3[m] = __fadd_rn(sP4[(m >> 4) - 1], sS3[m]);
    }
    __syncthreads();
    #pragma unroll
    for (int k = 0; k < 8; ++k) {
        int jj = t + k * 128;
        float p2 = sP2[jj];
        g_S2[b][jj] = (jj < 16) ? p2 : __fadd_rn(sS3[(jj >> 4) - 1], p2);
    }
}

// ---- S reconstruction (exact reference fl nesting) ----
__device__ __forceinline__ float recon_S(int b, int n) {
    float p0 = g_P0[b][n];
    const int r1i = n >> 4;
    if (r1i == 0) return p0;
    const int j = r1i - 1;
    float p1 = g_P1[b][j];
    const int r2 = j >> 4;
    float s1 = (r2 == 0) ? p1 : __fadd_rn(g_S2[b][r2 - 1], p1);
    return __fadd_rn(s1, p0);
}

// ---- k_main: packed f32x2 synthesis, 4 samples/thread ----
__global__ void __launch_bounds__(128) k_main(const float* __restrict__ amps,
                                              float* __restrict__ out) {
    const int b = blockIdx.y;
    const int n0 = blockIdx.x * 512;
    const int t = threadIdx.x;                   // 0..127

    float posF = __fmul_rn((float)n0, interp_c());
    const int i0f = (int)floorf(posF);

    __shared__ __align__(16) u64 sA0[2][32];
    __shared__ __align__(16) u64 sDF[2][32];
    if (t < 64) {
        int g = t >> 5;
        int s = t & 31;
        int r0 = min(i0f + g, FRAMES - 1);
        int r1 = min(r0 + 1, FRAMES - 1);
        const u64* rowA = (const u64*)(amps + ((size_t)b * FRAMES + r0) * NH);
        const u64* rowB = (const u64*)(amps + ((size_t)b * FRAMES + r1) * NH);
        u64 a0 = __ldg(rowA + s);
        u64 a1 = __ldg(rowB + s);
        sA0[g][s] = a0;
        sDF[g][s] = sub2(a1, a0);
    }

    const float TWO_PI_F = 6.283185307179586f;

    int   nS[4];
    int   gS[4];
    u64   w2[4], ph2[4];
    #pragma unroll
    for (int s = 0; s < 4; ++s) {
        const int n = n0 + t + s * 128;
        nS[s] = n;
        float ph = __fmul_rn(recon_S(b, n), TWO_PI_F);
        float pos = __fmul_rn((float)n, interp_c());
        float fi  = floorf(pos);
        int   i0  = (int)fi;
        float w   = __fadd_rn(pos, -fi);
        gS[s]  = i0 - i0f;                       // 0 or 1
        w2[s]  = pk(w, w);
        ph2[s] = pk(ph, ph);
    }

    __syncthreads();

    const float INV2PI = (float)(1.0 / 6.283185307179586);
    const float C1 = 6.283185482025146484375f;
    const float C2 = -1.7484556e-7f;
    const float MAGIC = 12582912.0f;             // 1.5 * 2^23

    u64 IV2 = pk(INV2PI, INV2PI);
    u64 MG2 = pk(MAGIC, MAGIC);
    u64 C1n = pk(-C1, -C1);
    u64 C2n = pk(-C2, -C2);
    u64 acc0[4], acc1[4];
    #pragma unroll
    for (int s = 0; s < 4; ++s) { acc0[s] = pk(0.0f, 0.0f); acc1[s] = pk(0.0f, 0.0f); }

    #pragma unroll
    for (int q = 0; q < NH / 4; ++q) {
        u64 h0 = pk((float)(4 * q + 1), (float)(4 * q + 2));
        u64 h1 = pk((float)(4 * q + 3), (float)(4 * q + 4));

        #pragma unroll
        for (int s = 0; s < 4; ++s) {
            ulonglong2 a0v = ((const ulonglong2*)sA0[gS[s]])[q];
            ulonglong2 dfv = ((const ulonglong2*)sDF[gS[s]])[q];
            u64 amp0 = fma2(w2[s], dfv.x, a0v.x);
            u64 amp1 = fma2(w2[s], dfv.y, a0v.y);

            {   u64 pr = mul2(ph2[s], h0);
                u64 tt = fma2(pr, IV2, MG2);
                u64 kf = sub2(tt, MG2);
                u64 r  = fma2(kf, C1n, pr);
                r      = fma2(kf, C2n, r);
                float rl, rh; upk(r, rl, rh);
                acc0[s] = fma2(pk(__sinf(rl), __sinf(rh)), amp0, acc0[s]);
            }
            {   u64 pr = mul2(ph2[s], h1);
                u64 tt = fma2(pr, IV2, MG2);
                u64 kf = sub2(tt, MG2);
                u64 r  = fma2(kf, C1n, pr);
                r      = fma2(kf, C2n, r);
                float rl, rh; upk(r, rl, rh);
                acc1[s] = fma2(pk(__sinf(rl), __sinf(rh)), amp1, acc1[s]);
            }
        }
    }
    #pragma unroll
    for (int s = 0; s < 4; ++s) {
        float a0l, a0h, a1l, a1h;
        upk(acc0[s], a0l, a0h);
        upk(acc1[s], a1l, a1h);
        out[(size_t)b * NS + nS[s]] = (a0l + a0h) + (a1l + a1h);
    }
}

extern "C" void kernel_launch(void* const* d_in, const int* in_sizes, int n_in,
                              void* d_out, int out_size) {
    const float* f0   = (const float*)d_in[0];   // (8, 512)
    const float* amps = (const float*)d_in[1];   // (8, 512, 64)
    float* out = (float*)d_out;                  // (8, 262144)

    k1<<<dim3(ROWS / 256, BATCH), 256>>>(f0);
    k2<<<BATCH, 128>>>();
    k_main<<<dim3(NS / 512, BATCH), 128>>>(amps, out);
}